// round 3
// baseline (speedup 1.0000x reference)
#include <cuda_runtime.h>
#include <cuda_bf16.h>
#include <math.h>

#define SEQ   128
#define BAT   32
#define EH    512
#define EO    256
#define HID   512
#define G3    1536
#define OUTD  256
#define MROWS (SEQ*BAT)
#define THRESH 1e-6f

typedef unsigned long long ull;

// ---------------- scratch (device globals; no allocation allowed) ----------
__device__ float g_emb[MROWS * EO];          // 4 MB
__device__ float g_xproj[MROWS * G3];        // 25 MB
__device__ float g_h[2][BAT * HID];          // ping-pong hidden state
__device__ unsigned g_bar_count = 0;         // monotonic across launches
__device__ unsigned g_bar_gen   = 0;         // monotonic across launches

// ---------------- f32x2 helpers -------------------------------------------
__device__ __forceinline__ ull pack2(float lo, float hi) {
    ull r; asm("mov.b64 %0, {%1, %2};" : "=l"(r) : "f"(lo), "f"(hi)); return r;
}
__device__ __forceinline__ float2 unpack2(ull v) {
    float2 r; asm("mov.b64 {%0, %1}, %2;" : "=f"(r.x), "=f"(r.y) : "l"(v)); return r;
}
__device__ __forceinline__ void fma2(ull& d, ull a, ull b) {
    asm("fma.rn.f32x2 %0, %1, %2, %3;" : "=l"(d) : "l"(a), "l"(b), "l"(d));
}
__device__ __forceinline__ float thr(float v) { return v > THRESH ? v : 0.0f; }

// ---------------- acquire/release helpers for the grid barrier ------------
__device__ __forceinline__ unsigned ld_acq(const unsigned* p) {
    unsigned v; asm volatile("ld.acquire.gpu.u32 %0, [%1];" : "=r"(v) : "l"(p)); return v;
}
__device__ __forceinline__ void st_rel(unsigned* p, unsigned v) {
    asm volatile("st.release.gpu.u32 [%0], %1;" :: "l"(p), "r"(v));
}

// ===========================================================================
// GEMM 1 (fused embedding): emb = thr( thr(W1[tok]+b1) @ W2 + b2 )
//   M=4096 K=512 N=256. Tile 128x64x16, 256 threads, 8x4 micro-tile (f32x2).
// ===========================================================================
__global__ __launch_bounds__(256) void gemm_embed_kernel(
    const int* __restrict__ tok, const float* __restrict__ W1,
    const float* __restrict__ b1, const float* __restrict__ W2,
    const float* __restrict__ b2)
{
    __shared__ __align__(16) float As[16][132];
    __shared__ __align__(16) float Bs[16][68];

    const int bm = blockIdx.x, bn = blockIdx.y;
    const int t  = threadIdx.x;
    const int tx = t & 15, ty = t >> 4;

    // A-load mapping: two rows per thread (row, row+64), k-segment aseg
    const int arow = t >> 2, aseg = t & 3;
    const int tk0 = tok[bm * 128 + arow];
    const int tk1 = tok[bm * 128 + arow + 64];
    const float* w1r0 = W1 + (size_t)tk0 * EH;
    const float* w1r1 = W1 + (size_t)tk1 * EH;
    // B-load mapping
    const int bk = t >> 4, bseg = t & 15;

    ull acc[8][2] = {};

    for (int kt = 0; kt < EH; kt += 16) {
        float4 bb = *(const float4*)(b1 + kt + aseg * 4);
        float4 a0 = *(const float4*)(w1r0 + kt + aseg * 4);
        float4 a1 = *(const float4*)(w1r1 + kt + aseg * 4);
        a0.x = thr(a0.x + bb.x); a0.y = thr(a0.y + bb.y);
        a0.z = thr(a0.z + bb.z); a0.w = thr(a0.w + bb.w);
        a1.x = thr(a1.x + bb.x); a1.y = thr(a1.y + bb.y);
        a1.z = thr(a1.z + bb.z); a1.w = thr(a1.w + bb.w);
        As[aseg * 4 + 0][arow] = a0.x;  As[aseg * 4 + 0][arow + 64] = a1.x;
        As[aseg * 4 + 1][arow] = a0.y;  As[aseg * 4 + 1][arow + 64] = a1.y;
        As[aseg * 4 + 2][arow] = a0.z;  As[aseg * 4 + 2][arow + 64] = a1.z;
        As[aseg * 4 + 3][arow] = a0.w;  As[aseg * 4 + 3][arow + 64] = a1.w;
        *(float4*)&Bs[bk][bseg * 4] =
            *(const float4*)(W2 + (size_t)(kt + bk) * EO + bn * 64 + bseg * 4);
        __syncthreads();
        #pragma unroll
        for (int kk = 0; kk < 16; kk++) {
            float4 av0 = *(const float4*)&As[kk][ty * 8];
            float4 av1 = *(const float4*)&As[kk][ty * 8 + 4];
            ulonglong2 bv = *(const ulonglong2*)&Bs[kk][tx * 4];
            ull a;
            a = pack2(av0.x, av0.x); fma2(acc[0][0], a, bv.x); fma2(acc[0][1], a, bv.y);
            a = pack2(av0.y, av0.y); fma2(acc[1][0], a, bv.x); fma2(acc[1][1], a, bv.y);
            a = pack2(av0.z, av0.z); fma2(acc[2][0], a, bv.x); fma2(acc[2][1], a, bv.y);
            a = pack2(av0.w, av0.w); fma2(acc[3][0], a, bv.x); fma2(acc[3][1], a, bv.y);
            a = pack2(av1.x, av1.x); fma2(acc[4][0], a, bv.x); fma2(acc[4][1], a, bv.y);
            a = pack2(av1.y, av1.y); fma2(acc[5][0], a, bv.x); fma2(acc[5][1], a, bv.y);
            a = pack2(av1.z, av1.z); fma2(acc[6][0], a, bv.x); fma2(acc[6][1], a, bv.y);
            a = pack2(av1.w, av1.w); fma2(acc[7][0], a, bv.x); fma2(acc[7][1], a, bv.y);
        }
        __syncthreads();
    }
    const int m0 = bm * 128 + ty * 8, n0 = bn * 64 + tx * 4;
    #pragma unroll
    for (int i = 0; i < 8; i++) {
        #pragma unroll
        for (int p = 0; p < 2; p++) {
            float2 v = unpack2(acc[i][p]);
            int n = n0 + p * 2;
            v.x = thr(v.x + b2[n]);
            v.y = thr(v.y + b2[n + 1]);
            *(float2*)&g_emb[(size_t)(m0 + i) * EO + n] = v;
        }
    }
}

// ===========================================================================
// GEMM 2 (NT): xproj = emb @ W_ih^T + b_ih   M=4096 K=256 N=1536
//   Tile 128x128x16, 256 threads, 8x8 micro-tile (f32x2).
// ===========================================================================
__global__ __launch_bounds__(256) void gemm_xproj_kernel(
    const float* __restrict__ W_ih, const float* __restrict__ b_ih)
{
    __shared__ __align__(16) float As[16][132];
    __shared__ __align__(16) float Bs[16][132];

    const int bm = blockIdx.x, bn = blockIdx.y;
    const int t  = threadIdx.x;
    const int tx = t & 15, ty = t >> 4;
    const int row = t >> 2, seg = t & 3;

    ull acc[8][4] = {};

    for (int kt = 0; kt < EO; kt += 16) {
        #pragma unroll
        for (int i = 0; i < 2; i++) {
            int r = row + i * 64;
            float4 a4 = *(const float4*)(g_emb + (size_t)(bm * 128 + r) * EO + kt + seg * 4);
            As[seg * 4 + 0][r] = a4.x;
            As[seg * 4 + 1][r] = a4.y;
            As[seg * 4 + 2][r] = a4.z;
            As[seg * 4 + 3][r] = a4.w;
            float4 b4 = *(const float4*)(W_ih + (size_t)(bn * 128 + r) * EO + kt + seg * 4);
            Bs[seg * 4 + 0][r] = b4.x;
            Bs[seg * 4 + 1][r] = b4.y;
            Bs[seg * 4 + 2][r] = b4.z;
            Bs[seg * 4 + 3][r] = b4.w;
        }
        __syncthreads();
        #pragma unroll
        for (int kk = 0; kk < 16; kk++) {
            float4 av0 = *(const float4*)&As[kk][ty * 8];
            float4 av1 = *(const float4*)&As[kk][ty * 8 + 4];
            ulonglong2 b01 = *(const ulonglong2*)&Bs[kk][tx * 8];
            ulonglong2 b23 = *(const ulonglong2*)&Bs[kk][tx * 8 + 4];
            ull a;
            a = pack2(av0.x, av0.x); fma2(acc[0][0], a, b01.x); fma2(acc[0][1], a, b01.y); fma2(acc[0][2], a, b23.x); fma2(acc[0][3], a, b23.y);
            a = pack2(av0.y, av0.y); fma2(acc[1][0], a, b01.x); fma2(acc[1][1], a, b01.y); fma2(acc[1][2], a, b23.x); fma2(acc[1][3], a, b23.y);
            a = pack2(av0.z, av0.z); fma2(acc[2][0], a, b01.x); fma2(acc[2][1], a, b01.y); fma2(acc[2][2], a, b23.x); fma2(acc[2][3], a, b23.y);
            a = pack2(av0.w, av0.w); fma2(acc[3][0], a, b01.x); fma2(acc[3][1], a, b01.y); fma2(acc[3][2], a, b23.x); fma2(acc[3][3], a, b23.y);
            a = pack2(av1.x, av1.x); fma2(acc[4][0], a, b01.x); fma2(acc[4][1], a, b01.y); fma2(acc[4][2], a, b23.x); fma2(acc[4][3], a, b23.y);
            a = pack2(av1.y, av1.y); fma2(acc[5][0], a, b01.x); fma2(acc[5][1], a, b01.y); fma2(acc[5][2], a, b23.x); fma2(acc[5][3], a, b23.y);
            a = pack2(av1.z, av1.z); fma2(acc[6][0], a, b01.x); fma2(acc[6][1], a, b01.y); fma2(acc[6][2], a, b23.x); fma2(acc[6][3], a, b23.y);
            a = pack2(av1.w, av1.w); fma2(acc[7][0], a, b01.x); fma2(acc[7][1], a, b01.y); fma2(acc[7][2], a, b23.x); fma2(acc[7][3], a, b23.y);
        }
        __syncthreads();
    }
    const int m0 = bm * 128 + ty * 8, n0 = bn * 128 + tx * 8;
    #pragma unroll
    for (int i = 0; i < 8; i++) {
        #pragma unroll
        for (int p = 0; p < 4; p++) {
            float2 v = unpack2(acc[i][p]);
            int n = n0 + p * 2;
            v.x += b_ih[n];
            v.y += b_ih[n + 1];
            *(float2*)&g_xproj[(size_t)(m0 + i) * G3 + n] = v;
        }
    }
}

// ===========================================================================
// GRU recurrence: persistent kernel, 128 CTAs x 128 threads.
// CTA = (bg 0..3, jg 0..31): owns b in [bg*8,+8), j in [jg*16,+16).
// Thread = (j = t>>3 in 0..15, ks = t&7 k-split). Each thread accumulates
// ALL 8 batch rows over its k-chunk of 64, reusing W regs across b.
// shfl.bfly reduction over the 8 ks lanes (contiguous in warp).
// Head GEMM folded into the epilogue.
// ===========================================================================
#define GRU_NCTA   128
#define GRU_WS     (3 * 128 * 16 * 4)      // floats (96 KB)
#define GRU_HSTR   516
#define GRU_SMEMB  ((GRU_WS + 8 * GRU_HSTR) * 4)

__global__ __launch_bounds__(128, 1) void gru_kernel(
    const float* __restrict__ W_hh, const float* __restrict__ b_hh,
    const float* __restrict__ W3,   const float* __restrict__ b3,
    float* __restrict__ out)
{
    extern __shared__ __align__(16) float smem[];
    float* w_s = smem;                 // [gate][kq][j16][4k]
    float* h_s = smem + GRU_WS;        // [8][516]

    const int t  = threadIdx.x;
    const int jg = blockIdx.x & 31;
    const int bg = blockIdx.x >> 5;

    unsigned gen0 = 0;
    if (t == 0) gen0 = *(volatile unsigned*)&g_bar_gen;

    // stage W_hh slice (once for all 128 steps)
    for (int idx = t; idx < 3 * 16 * 128; idx += 128) {
        int kq = idx & 127;
        int jj = (idx >> 7) & 15;
        int g  = idx >> 11;
        float4 v = *(const float4*)(W_hh + ((size_t)(g * HID + jg * 16 + jj)) * HID + kq * 4);
        *(float4*)(w_s + ((g * 128 + kq) * 16 + jj) * 4) = v;
    }
    // zero-init our slice of h buffer 0
    g_h[0][(bg * 8 + (t >> 4)) * HID + jg * 16 + (t & 15)] = 0.0f;

    // ---- grid barrier (monotonic counters, acquire-poll) ----
    #define GRID_BAR(BI) do {                                              \
        __syncthreads();                                                   \
        if (t == 0) {                                                      \
            __threadfence();                                               \
            unsigned prev = atomicAdd(&g_bar_count, 1u);                   \
            unsigned tgt = gen0 + (unsigned)(BI) + 1u;                     \
            if ((prev & (GRU_NCTA - 1u)) == GRU_NCTA - 1u) {               \
                st_rel(&g_bar_gen, tgt);                                   \
            } else {                                                       \
                while ((int)(ld_acq(&g_bar_gen) - tgt) < 0) { }            \
            }                                                              \
        }                                                                  \
        __syncthreads();                                                   \
    } while (0)

    GRID_BAR(0);

    const int j  = t >> 3;      // 0..15
    const int ks = t & 7;       // 0..7 (k split; 8 contiguous lanes)
    const int jglob = jg * 16 + j;
    const int bloc  = ks;       // this thread finalizes batch row bg*8+ks
    const int bglob = bg * 8 + ks;

    const float bhr = b_hh[jglob];
    const float bhz = b_hh[HID + jglob];
    const float bhn = b_hh[2 * HID + jglob];

    const float* wr_p = w_s + j * 4;
    const float* wz_p = w_s + 128 * 64 + j * 4;
    const float* wn_p = w_s + 2 * 128 * 64 + j * 4;
    const int kq0 = ks * 16;

    for (int step = 0; step < SEQ; step++) {
        const float* cur = g_h[step & 1];
        float* nxt = g_h[(step & 1) ^ 1];

        // restage h slice (written by other SMs -> bypass L1)
        for (int r = t; r < 8 * 128; r += 128) {
            int rb = r >> 7, rk = r & 127;
            float4 v = __ldcg((const float4*)(cur + (size_t)(bg * 8 + rb) * HID + rk * 4));
            *(float4*)(h_s + rb * GRU_HSTR + rk * 4) = v;
        }
        __syncthreads();

        ull acc[8][3];
        #pragma unroll
        for (int b = 0; b < 8; b++) { acc[b][0] = 0; acc[b][1] = 0; acc[b][2] = 0; }

        #pragma unroll 2
        for (int i = 0; i < 16; i++) {
            int kq = kq0 + i;
            ulonglong2 wr = *(const ulonglong2*)(wr_p + kq * 64);
            ulonglong2 wz = *(const ulonglong2*)(wz_p + kq * 64);
            ulonglong2 wn = *(const ulonglong2*)(wn_p + kq * 64);
            #pragma unroll
            for (int b = 0; b < 8; b++) {
                ulonglong2 hv = *(const ulonglong2*)(h_s + b * GRU_HSTR + kq * 4);
                fma2(acc[b][0], hv.x, wr.x); fma2(acc[b][0], hv.y, wr.y);
                fma2(acc[b][1], hv.x, wz.x); fma2(acc[b][1], hv.y, wz.y);
                fma2(acc[b][2], hv.x, wn.x); fma2(acc[b][2], hv.y, wn.y);
            }
        }

        // collapse f32x2 halves, then bfly-reduce over 8 ks lanes
        float s[8][3];
        #pragma unroll
        for (int b = 0; b < 8; b++)
            #pragma unroll
            for (int g = 0; g < 3; g++) {
                float2 v = unpack2(acc[b][g]);
                s[b][g] = v.x + v.y;
            }
        #pragma unroll
        for (int off = 4; off >= 1; off >>= 1)
            #pragma unroll
            for (int b = 0; b < 8; b++)
                #pragma unroll
                for (int g = 0; g < 3; g++)
                    s[b][g] += __shfl_xor_sync(0xffffffffu, s[b][g], off);

        // select this thread's batch row (predicated, no spill)
        float ghr = 0.f, ghz = 0.f, ghn = 0.f;
        #pragma unroll
        for (int b = 0; b < 8; b++)
            if (b == bloc) { ghr = s[b][0]; ghz = s[b][1]; ghn = s[b][2]; }
        ghr += bhr; ghz += bhz; ghn += bhn;

        size_t xb = ((size_t)(step * BAT + bglob)) * G3 + jglob;
        float xr = __ldcg(g_xproj + xb);
        float xz = __ldcg(g_xproj + xb + HID);
        float xn = __ldcg(g_xproj + xb + 2 * HID);

        float r = 1.0f / (1.0f + expf(-(xr + ghr)));
        float z = 1.0f / (1.0f + expf(-(xz + ghz)));
        float n = tanhf(xn + r * ghn);
        float hprev = h_s[bloc * GRU_HSTR + jglob];
        float hnew  = (1.0f - z) * n + z * hprev;

        nxt[(size_t)bglob * HID + jglob] = hnew;
        GRID_BAR(step + 1);
    }

    // ---- head epilogue: out[b][o] = h[b] . W3[:,o] + b3[o] ----
    // CTA covers b in [bg*8,+8), o in [jg*8,+8). SEQ even -> h in g_h[0].
    for (int r = t; r < 8 * 128; r += 128) {
        int rb = r >> 7, rk = r & 127;
        float4 v = __ldcg((const float4*)(g_h[0] + (size_t)(bg * 8 + rb) * HID + rk * 4));
        *(float4*)(h_s + rb * GRU_HSTR + rk * 4) = v;
    }
    __syncthreads();

    {
        const int o  = t & 7;        // 0..7
        const int kc = t >> 3;       // 0..15, k-chunk of 32
        float part[8];
        #pragma unroll
        for (int b = 0; b < 8; b++) part[b] = 0.f;
        for (int kk = kc * 32; kk < kc * 32 + 32; kk++) {
            float w = __ldg(W3 + (size_t)kk * OUTD + jg * 8 + o);
            #pragma unroll
            for (int b = 0; b < 8; b++)
                part[b] = fmaf(h_s[b * GRU_HSTR + kk], w, part[b]);
        }
        float* red = w_s;  // scratch [16][8][8]
        #pragma unroll
        for (int b = 0; b < 8; b++) red[(kc * 8 + o) * 8 + b] = part[b];
        __syncthreads();
        if (t < 64) {
            int oo = t & 7, bb = t >> 3;
            float sum = b3[jg * 8 + oo];
            #pragma unroll
            for (int k2 = 0; k2 < 16; k2++) sum += red[(k2 * 8 + oo) * 8 + bb];
            out[(bg * 8 + bb) * OUTD + jg * 8 + oo] = sum;
        }
    }
}

// ===========================================================================
extern "C" void kernel_launch(void* const* d_in, const int* in_sizes, int n_in,
                              void* d_out, int out_size)
{
    const int*   input = (const int*)  d_in[0];
    const float* W1    = (const float*)d_in[1];
    const float* b1    = (const float*)d_in[2];
    const float* W2    = (const float*)d_in[3];
    const float* b2    = (const float*)d_in[4];
    const float* W_ih  = (const float*)d_in[5];
    const float* W_hh  = (const float*)d_in[6];
    const float* b_ih  = (const float*)d_in[7];
    const float* b_hh  = (const float*)d_in[8];
    const float* W3    = (const float*)d_in[9];
    const float* b3    = (const float*)d_in[10];
    float* out = (float*)d_out;

    static int configured = 0;
    if (!configured) {
        cudaFuncSetAttribute(gru_kernel,
            cudaFuncAttributeMaxDynamicSharedMemorySize, GRU_SMEMB);
        configured = 1;
    }

    dim3 g1(MROWS / 128, EO / 64);
    gemm_embed_kernel<<<g1, 256>>>(input, W1, b1, W2, b2);

    dim3 g2(MROWS / 128, G3 / 128);
    gemm_xproj_kernel<<<g2, 256>>>(W_ih, b_ih);

    gru_kernel<<<GRU_NCTA, 128, GRU_SMEMB>>>(W_hh, b_hh, W3, b3, out);
}

// round 4
// speedup vs baseline: 1.8827x; 1.8827x over previous
#include <cuda_runtime.h>
#include <cuda_bf16.h>
#include <math.h>

#define SEQ   128
#define BAT   32
#define EH    512
#define EO    256
#define HID   512
#define G3    1536
#define OUTD  256
#define MROWS (SEQ*BAT)
#define THRESH 1e-6f

typedef unsigned long long ull;

// ---------------- scratch (device globals; no allocation allowed) ----------
__device__ float g_emb[MROWS * EO];          // 4 MB
__device__ float g_xproj[MROWS * G3];        // 25 MB
__device__ float g_h[2][BAT * HID];          // ping-pong hidden state
// distributed barrier state (monotonic across graph replays)
__device__ __align__(128) unsigned g_flags[128 * 32];  // one flag / CTA, 128B apart
__device__ unsigned g_gen2 = 0;

// ---------------- f32x2 helpers -------------------------------------------
__device__ __forceinline__ ull pack2(float lo, float hi) {
    ull r; asm("mov.b64 %0, {%1, %2};" : "=l"(r) : "f"(lo), "f"(hi)); return r;
}
__device__ __forceinline__ float2 unpack2(ull v) {
    float2 r; asm("mov.b64 {%0, %1}, %2;" : "=f"(r.x), "=f"(r.y) : "l"(v)); return r;
}
__device__ __forceinline__ void fma2(ull& d, ull a, ull b) {
    asm("fma.rn.f32x2 %0, %1, %2, %3;" : "=l"(d) : "l"(a), "l"(b), "l"(d));
}
__device__ __forceinline__ float thr(float v) { return v > THRESH ? v : 0.0f; }

// ---------------- acquire/release helpers ----------------------------------
__device__ __forceinline__ unsigned ld_acq(const unsigned* p) {
    unsigned v; asm volatile("ld.acquire.gpu.u32 %0, [%1];" : "=r"(v) : "l"(p)); return v;
}
__device__ __forceinline__ void st_rel(unsigned* p, unsigned v) {
    asm volatile("st.release.gpu.u32 [%0], %1;" :: "l"(p), "r"(v));
}

// ===========================================================================
// GEMM 1 (fused embedding): emb = thr( thr(W1[tok]+b1) @ W2 + b2 )
//   M=4096 K=512 N=256. Tile 128x64x16, 256 threads, 8x4 micro-tile (f32x2).
// ===========================================================================
__global__ __launch_bounds__(256) void gemm_embed_kernel(
    const int* __restrict__ tok, const float* __restrict__ W1,
    const float* __restrict__ b1, const float* __restrict__ W2,
    const float* __restrict__ b2)
{
    __shared__ __align__(16) float As[16][132];
    __shared__ __align__(16) float Bs[16][68];

    const int bm = blockIdx.x, bn = blockIdx.y;
    const int t  = threadIdx.x;
    const int tx = t & 15, ty = t >> 4;

    const int arow = t >> 2, aseg = t & 3;
    const int tk0 = tok[bm * 128 + arow];
    const int tk1 = tok[bm * 128 + arow + 64];
    const float* w1r0 = W1 + (size_t)tk0 * EH;
    const float* w1r1 = W1 + (size_t)tk1 * EH;
    const int bk = t >> 4, bseg = t & 15;

    ull acc[8][2] = {};

    for (int kt = 0; kt < EH; kt += 16) {
        float4 bb = *(const float4*)(b1 + kt + aseg * 4);
        float4 a0 = *(const float4*)(w1r0 + kt + aseg * 4);
        float4 a1 = *(const float4*)(w1r1 + kt + aseg * 4);
        a0.x = thr(a0.x + bb.x); a0.y = thr(a0.y + bb.y);
        a0.z = thr(a0.z + bb.z); a0.w = thr(a0.w + bb.w);
        a1.x = thr(a1.x + bb.x); a1.y = thr(a1.y + bb.y);
        a1.z = thr(a1.z + bb.z); a1.w = thr(a1.w + bb.w);
        As[aseg * 4 + 0][arow] = a0.x;  As[aseg * 4 + 0][arow + 64] = a1.x;
        As[aseg * 4 + 1][arow] = a0.y;  As[aseg * 4 + 1][arow + 64] = a1.y;
        As[aseg * 4 + 2][arow] = a0.z;  As[aseg * 4 + 2][arow + 64] = a1.z;
        As[aseg * 4 + 3][arow] = a0.w;  As[aseg * 4 + 3][arow + 64] = a1.w;
        *(float4*)&Bs[bk][bseg * 4] =
            *(const float4*)(W2 + (size_t)(kt + bk) * EO + bn * 64 + bseg * 4);
        __syncthreads();
        #pragma unroll
        for (int kk = 0; kk < 16; kk++) {
            float4 av0 = *(const float4*)&As[kk][ty * 8];
            float4 av1 = *(const float4*)&As[kk][ty * 8 + 4];
            ulonglong2 bv = *(const ulonglong2*)&Bs[kk][tx * 4];
            ull a;
            a = pack2(av0.x, av0.x); fma2(acc[0][0], a, bv.x); fma2(acc[0][1], a, bv.y);
            a = pack2(av0.y, av0.y); fma2(acc[1][0], a, bv.x); fma2(acc[1][1], a, bv.y);
            a = pack2(av0.z, av0.z); fma2(acc[2][0], a, bv.x); fma2(acc[2][1], a, bv.y);
            a = pack2(av0.w, av0.w); fma2(acc[3][0], a, bv.x); fma2(acc[3][1], a, bv.y);
            a = pack2(av1.x, av1.x); fma2(acc[4][0], a, bv.x); fma2(acc[4][1], a, bv.y);
            a = pack2(av1.y, av1.y); fma2(acc[5][0], a, bv.x); fma2(acc[5][1], a, bv.y);
            a = pack2(av1.z, av1.z); fma2(acc[6][0], a, bv.x); fma2(acc[6][1], a, bv.y);
            a = pack2(av1.w, av1.w); fma2(acc[7][0], a, bv.x); fma2(acc[7][1], a, bv.y);
        }
        __syncthreads();
    }
    const int m0 = bm * 128 + ty * 8, n0 = bn * 64 + tx * 4;
    #pragma unroll
    for (int i = 0; i < 8; i++) {
        #pragma unroll
        for (int p = 0; p < 2; p++) {
            float2 v = unpack2(acc[i][p]);
            int n = n0 + p * 2;
            v.x = thr(v.x + b2[n]);
            v.y = thr(v.y + b2[n + 1]);
            *(float2*)&g_emb[(size_t)(m0 + i) * EO + n] = v;
        }
    }
}

// ===========================================================================
// GEMM 2 (NT): xproj = emb @ W_ih^T + b_ih   M=4096 K=256 N=1536
//   Tile 128x128x16, 256 threads, 8x8 micro-tile (f32x2).
// ===========================================================================
__global__ __launch_bounds__(256) void gemm_xproj_kernel(
    const float* __restrict__ W_ih, const float* __restrict__ b_ih)
{
    __shared__ __align__(16) float As[16][132];
    __shared__ __align__(16) float Bs[16][132];

    const int bm = blockIdx.x, bn = blockIdx.y;
    const int t  = threadIdx.x;
    const int tx = t & 15, ty = t >> 4;
    const int row = t >> 2, seg = t & 3;

    ull acc[8][4] = {};

    for (int kt = 0; kt < EO; kt += 16) {
        #pragma unroll
        for (int i = 0; i < 2; i++) {
            int r = row + i * 64;
            float4 a4 = *(const float4*)(g_emb + (size_t)(bm * 128 + r) * EO + kt + seg * 4);
            As[seg * 4 + 0][r] = a4.x;
            As[seg * 4 + 1][r] = a4.y;
            As[seg * 4 + 2][r] = a4.z;
            As[seg * 4 + 3][r] = a4.w;
            float4 b4 = *(const float4*)(W_ih + (size_t)(bn * 128 + r) * EO + kt + seg * 4);
            Bs[seg * 4 + 0][r] = b4.x;
            Bs[seg * 4 + 1][r] = b4.y;
            Bs[seg * 4 + 2][r] = b4.z;
            Bs[seg * 4 + 3][r] = b4.w;
        }
        __syncthreads();
        #pragma unroll
        for (int kk = 0; kk < 16; kk++) {
            float4 av0 = *(const float4*)&As[kk][ty * 8];
            float4 av1 = *(const float4*)&As[kk][ty * 8 + 4];
            ulonglong2 b01 = *(const ulonglong2*)&Bs[kk][tx * 8];
            ulonglong2 b23 = *(const ulonglong2*)&Bs[kk][tx * 8 + 4];
            ull a;
            a = pack2(av0.x, av0.x); fma2(acc[0][0], a, b01.x); fma2(acc[0][1], a, b01.y); fma2(acc[0][2], a, b23.x); fma2(acc[0][3], a, b23.y);
            a = pack2(av0.y, av0.y); fma2(acc[1][0], a, b01.x); fma2(acc[1][1], a, b01.y); fma2(acc[1][2], a, b23.x); fma2(acc[1][3], a, b23.y);
            a = pack2(av0.z, av0.z); fma2(acc[2][0], a, b01.x); fma2(acc[2][1], a, b01.y); fma2(acc[2][2], a, b23.x); fma2(acc[2][3], a, b23.y);
            a = pack2(av0.w, av0.w); fma2(acc[3][0], a, b01.x); fma2(acc[3][1], a, b01.y); fma2(acc[3][2], a, b23.x); fma2(acc[3][3], a, b23.y);
            a = pack2(av1.x, av1.x); fma2(acc[4][0], a, b01.x); fma2(acc[4][1], a, b01.y); fma2(acc[4][2], a, b23.x); fma2(acc[4][3], a, b23.y);
            a = pack2(av1.y, av1.y); fma2(acc[5][0], a, b01.x); fma2(acc[5][1], a, b01.y); fma2(acc[5][2], a, b23.x); fma2(acc[5][3], a, b23.y);
            a = pack2(av1.z, av1.z); fma2(acc[6][0], a, b01.x); fma2(acc[6][1], a, b01.y); fma2(acc[6][2], a, b23.x); fma2(acc[6][3], a, b23.y);
            a = pack2(av1.w, av1.w); fma2(acc[7][0], a, b01.x); fma2(acc[7][1], a, b01.y); fma2(acc[7][2], a, b23.x); fma2(acc[7][3], a, b23.y);
        }
        __syncthreads();
    }
    const int m0 = bm * 128 + ty * 8, n0 = bn * 128 + tx * 8;
    #pragma unroll
    for (int i = 0; i < 8; i++) {
        #pragma unroll
        for (int p = 0; p < 4; p++) {
            float2 v = unpack2(acc[i][p]);
            int n = n0 + p * 2;
            v.x += b_ih[n];
            v.y += b_ih[n + 1];
            *(float2*)&g_xproj[(size_t)(m0 + i) * G3 + n] = v;
        }
    }
}

// ===========================================================================
// GRU recurrence: persistent kernel, 128 CTAs x 128 threads.
// CTA = (bg 0..3, jg 0..31): owns b in [bg*8,+8), j in [jg*16,+16).
// R1's conflict-free mapping: thread = one (bl, j) output, full k=512.
// Distributed-flag grid barrier (no atomic contention).
// Head GEMM folded into the epilogue.
// ===========================================================================
#define GRU_NCTA   128
#define GRU_WS     (3 * 128 * 16 * 4)      // floats (96 KB)
#define GRU_HSTR   516
#define GRU_SMEMB  ((GRU_WS + 8 * GRU_HSTR) * 4)

__global__ __launch_bounds__(128, 1) void gru_kernel(
    const float* __restrict__ W_hh, const float* __restrict__ b_hh,
    const float* __restrict__ W3,   const float* __restrict__ b3,
    float* __restrict__ out)
{
    extern __shared__ __align__(16) float smem[];
    float* w_s = smem;                 // [gate][kq][j16][4]
    float* h_s = smem + GRU_WS;        // [8][516]

    const int t   = threadIdx.x;
    const int bid = blockIdx.x;
    const int jg  = bid & 31;
    const int bg  = bid >> 5;

    // barrier bases (stable: previous launch fully retired before we start)
    unsigned fbase_t = g_flags[t * 32];           // CTA0 poller base (t -> CTA t)
    unsigned fbase_c = g_flags[bid * 32];         // own-flag base
    unsigned gbase   = *(volatile unsigned*)&g_gen2;

    // stage W_hh slice (once for all 128 steps)
    for (int idx = t; idx < 3 * 16 * 128; idx += 128) {
        int kq = idx & 127;
        int jj = (idx >> 7) & 15;
        int g  = idx >> 11;
        float4 v = *(const float4*)(W_hh + ((size_t)(g * HID + jg * 16 + jj)) * HID + kq * 4);
        *(float4*)(w_s + ((g * 128 + kq) * 16 + jj) * 4) = v;
    }
    // zero-init our slice of h buffer 0
    g_h[0][(bg * 8 + (t >> 4)) * HID + jg * 16 + (t & 15)] = 0.0f;

    // ---- distributed grid barrier ----
    // arrival: own-flag release store (no contention). CTA0 threads 1..127
    // poll the 127 peer flags in parallel, then t0 releases g_gen2.
    #define GRID_BAR(BI) do {                                                  \
        __syncthreads();                                                       \
        if (bid == 0) {                                                        \
            unsigned ftgt = fbase_t + (unsigned)(BI);                          \
            if (t >= 1) {                                                      \
                while ((int)(ld_acq(&g_flags[t * 32]) - ftgt) < 0) { }         \
            }                                                                  \
            __syncthreads();                                                   \
            if (t == 0) st_rel(&g_gen2, gbase + (unsigned)(BI));               \
        } else {                                                               \
            if (t == 0) {                                                      \
                st_rel(&g_flags[bid * 32], fbase_c + (unsigned)(BI));          \
                unsigned gtgt = gbase + (unsigned)(BI);                        \
                while ((int)(ld_acq(&g_gen2) - gtgt) < 0) { }                  \
            }                                                                  \
            __syncthreads();                                                   \
        }                                                                      \
    } while (0)

    GRID_BAR(1);

    const int j     = (t & 3) + ((t >> 5) << 2);
    const int bl    = (t >> 2) & 7;
    const int b     = bg * 8 + bl;
    const int jglob = jg * 16 + j;

    const float bhr = b_hh[jglob];
    const float bhz = b_hh[HID + jglob];
    const float bhn = b_hh[2 * HID + jglob];

    const float* hsrow = h_s + bl * GRU_HSTR;
    const float* wr_p  = w_s + j * 4;
    const float* wz_p  = w_s + 128 * 64 + j * 4;
    const float* wn_p  = w_s + 2 * 128 * 64 + j * 4;

    for (int step = 0; step < SEQ; step++) {
        const float* cur = g_h[step & 1];
        float* nxt = g_h[(step & 1) ^ 1];

        // prefetch this step's xproj early (hide L2 latency behind restage+MMA)
        size_t xb = ((size_t)(step * BAT + b)) * G3 + jglob;
        float xr = __ldcg(g_xproj + xb);
        float xz = __ldcg(g_xproj + xb + HID);
        float xn = __ldcg(g_xproj + xb + 2 * HID);

        // restage h slice (written by other SMs -> bypass L1)
        for (int r = t; r < 8 * 128; r += 128) {
            int rb = r >> 7, rk = r & 127;
            float4 v = __ldcg((const float4*)(cur + (size_t)(bg * 8 + rb) * HID + rk * 4));
            *(float4*)(h_s + rb * GRU_HSTR + rk * 4) = v;
        }
        __syncthreads();

        ull ar0 = 0, ar1 = 0, az0 = 0, az1 = 0, an0 = 0, an1 = 0;
        #pragma unroll 4
        for (int kq = 0; kq < 128; kq++) {
            ulonglong2 hv = *(const ulonglong2*)(hsrow + kq * 4);
            ulonglong2 wr = *(const ulonglong2*)(wr_p + kq * 64);
            ulonglong2 wz = *(const ulonglong2*)(wz_p + kq * 64);
            ulonglong2 wn = *(const ulonglong2*)(wn_p + kq * 64);
            fma2(ar0, hv.x, wr.x); fma2(ar1, hv.y, wr.y);
            fma2(az0, hv.x, wz.x); fma2(az1, hv.y, wz.y);
            fma2(an0, hv.x, wn.x); fma2(an1, hv.y, wn.y);
        }
        float2 fr0 = unpack2(ar0), fr1 = unpack2(ar1);
        float2 fz0 = unpack2(az0), fz1 = unpack2(az1);
        float2 fn0 = unpack2(an0), fn1 = unpack2(an1);
        float ghr = (fr0.x + fr0.y) + (fr1.x + fr1.y) + bhr;
        float ghz = (fz0.x + fz0.y) + (fz1.x + fz1.y) + bhz;
        float ghn = (fn0.x + fn0.y) + (fn1.x + fn1.y) + bhn;

        float r = 1.0f / (1.0f + expf(-(xr + ghr)));
        float z = 1.0f / (1.0f + expf(-(xz + ghz)));
        float n = tanhf(xn + r * ghn);
        float hprev = hsrow[jglob];
        float hnew  = (1.0f - z) * n + z * hprev;

        nxt[(size_t)b * HID + jglob] = hnew;
        GRID_BAR(step + 2);
    }

    // ---- head epilogue: out[b][o] = h[b] . W3[:,o] + b3[o] ----
    // CTA covers b in [bg*8,+8), o in [jg*8,+8). SEQ even -> h in g_h[0].
    for (int r = t; r < 8 * 128; r += 128) {
        int rb = r >> 7, rk = r & 127;
        float4 v = __ldcg((const float4*)(g_h[0] + (size_t)(bg * 8 + rb) * HID + rk * 4));
        *(float4*)(h_s + rb * GRU_HSTR + rk * 4) = v;
    }
    __syncthreads();

    {
        const int o  = t & 7;        // 0..7
        const int kc = t >> 3;       // 0..15, k-chunk of 32
        float part[8];
        #pragma unroll
        for (int bb = 0; bb < 8; bb++) part[bb] = 0.f;
        for (int kk = kc * 32; kk < kc * 32 + 32; kk++) {
            float w = __ldg(W3 + (size_t)kk * OUTD + jg * 8 + o);
            #pragma unroll
            for (int bb = 0; bb < 8; bb++)
                part[bb] = fmaf(h_s[bb * GRU_HSTR + kk], w, part[bb]);
        }
        float* red = w_s;  // scratch [16][8][8] (W no longer needed)
        #pragma unroll
        for (int bb = 0; bb < 8; bb++) red[(kc * 8 + o) * 8 + bb] = part[bb];
        __syncthreads();
        if (t < 64) {
            int oo = t & 7, bb = t >> 3;
            float sum = b3[jg * 8 + oo];
            #pragma unroll
            for (int k2 = 0; k2 < 16; k2++) sum += red[(k2 * 8 + oo) * 8 + bb];
            out[(bg * 8 + bb) * OUTD + jg * 8 + oo] = sum;
        }
    }
}

// ===========================================================================
extern "C" void kernel_launch(void* const* d_in, const int* in_sizes, int n_in,
                              void* d_out, int out_size)
{
    const int*   input = (const int*)  d_in[0];
    const float* W1    = (const float*)d_in[1];
    const float* b1    = (const float*)d_in[2];
    const float* W2    = (const float*)d_in[3];
    const float* b2    = (const float*)d_in[4];
    const float* W_ih  = (const float*)d_in[5];
    const float* W_hh  = (const float*)d_in[6];
    const float* b_ih  = (const float*)d_in[7];
    const float* b_hh  = (const float*)d_in[8];
    const float* W3    = (const float*)d_in[9];
    const float* b3    = (const float*)d_in[10];
    float* out = (float*)d_out;

    static int configured = 0;
    if (!configured) {
        cudaFuncSetAttribute(gru_kernel,
            cudaFuncAttributeMaxDynamicSharedMemorySize, GRU_SMEMB);
        configured = 1;
    }

    dim3 g1(MROWS / 128, EO / 64);
    gemm_embed_kernel<<<g1, 256>>>(input, W1, b1, W2, b2);

    dim3 g2(MROWS / 128, G3 / 128);
    gemm_xproj_kernel<<<g2, 256>>>(W_ih, b_ih);

    gru_kernel<<<GRU_NCTA, 128, GRU_SMEMB>>>(W_hh, b_hh, W3, b3, out);
}

// round 5
// speedup vs baseline: 2.4685x; 1.3111x over previous
#include <cuda_runtime.h>
#include <cuda_bf16.h>
#include <math.h>

#define SEQ   128
#define BAT   32
#define EH    512
#define EO    256
#define HID   512
#define G3    1536
#define OUTD  256
#define MROWS (SEQ*BAT)
#define THRESH 1e-6f

typedef unsigned long long ull;

// ---------------- scratch (device globals; no allocation allowed) ----------
__device__ float g_emb[MROWS * EO];          // 4 MB
__device__ float g_xproj[MROWS * G3];        // 25 MB
__device__ float g_h[2][BAT * HID];          // ping-pong hidden state
// per-bg barrier state: absolute-valued, reset to 0 at end of each launch
__device__ __align__(128) unsigned g_bflags[128 * 32]; // flag per CTA, 128B apart
__device__ __align__(128) unsigned g_bgen[4 * 32];     // gen per bg group

// ---------------- f32x2 helpers -------------------------------------------
__device__ __forceinline__ ull pack2(float lo, float hi) {
    ull r; asm("mov.b64 %0, {%1, %2};" : "=l"(r) : "f"(lo), "f"(hi)); return r;
}
__device__ __forceinline__ float2 unpack2(ull v) {
    float2 r; asm("mov.b64 {%0, %1}, %2;" : "=f"(r.x), "=f"(r.y) : "l"(v)); return r;
}
__device__ __forceinline__ void fma2(ull& d, ull a, ull b) {
    asm("fma.rn.f32x2 %0, %1, %2, %3;" : "=l"(d) : "l"(a), "l"(b), "l"(d));
}
__device__ __forceinline__ float thr(float v) { return v > THRESH ? v : 0.0f; }

// ---------------- acquire/release helpers ----------------------------------
__device__ __forceinline__ unsigned ld_acq(const unsigned* p) {
    unsigned v; asm volatile("ld.acquire.gpu.u32 %0, [%1];" : "=r"(v) : "l"(p)); return v;
}
__device__ __forceinline__ void st_rel(unsigned* p, unsigned v) {
    asm volatile("st.release.gpu.u32 [%0], %1;" :: "l"(p), "r"(v));
}

// ===========================================================================
// GEMM 1 (fused embedding): emb = thr( thr(W1[tok]+b1) @ W2 + b2 )
//   M=4096 K=512 N=256. Tile 128x64x16, 256 threads, 8x4 micro-tile (f32x2).
// ===========================================================================
__global__ __launch_bounds__(256) void gemm_embed_kernel(
    const int* __restrict__ tok, const float* __restrict__ W1,
    const float* __restrict__ b1, const float* __restrict__ W2,
    const float* __restrict__ b2)
{
    __shared__ __align__(16) float As[16][132];
    __shared__ __align__(16) float Bs[16][68];

    const int bm = blockIdx.x, bn = blockIdx.y;
    const int t  = threadIdx.x;
    const int tx = t & 15, ty = t >> 4;

    const int arow = t >> 2, aseg = t & 3;
    const int tk0 = tok[bm * 128 + arow];
    const int tk1 = tok[bm * 128 + arow + 64];
    const float* w1r0 = W1 + (size_t)tk0 * EH;
    const float* w1r1 = W1 + (size_t)tk1 * EH;
    const int bk = t >> 4, bseg = t & 15;

    ull acc[8][2] = {};

    for (int kt = 0; kt < EH; kt += 16) {
        float4 bb = *(const float4*)(b1 + kt + aseg * 4);
        float4 a0 = *(const float4*)(w1r0 + kt + aseg * 4);
        float4 a1 = *(const float4*)(w1r1 + kt + aseg * 4);
        a0.x = thr(a0.x + bb.x); a0.y = thr(a0.y + bb.y);
        a0.z = thr(a0.z + bb.z); a0.w = thr(a0.w + bb.w);
        a1.x = thr(a1.x + bb.x); a1.y = thr(a1.y + bb.y);
        a1.z = thr(a1.z + bb.z); a1.w = thr(a1.w + bb.w);
        As[aseg * 4 + 0][arow] = a0.x;  As[aseg * 4 + 0][arow + 64] = a1.x;
        As[aseg * 4 + 1][arow] = a0.y;  As[aseg * 4 + 1][arow + 64] = a1.y;
        As[aseg * 4 + 2][arow] = a0.z;  As[aseg * 4 + 2][arow + 64] = a1.z;
        As[aseg * 4 + 3][arow] = a0.w;  As[aseg * 4 + 3][arow + 64] = a1.w;
        *(float4*)&Bs[bk][bseg * 4] =
            *(const float4*)(W2 + (size_t)(kt + bk) * EO + bn * 64 + bseg * 4);
        __syncthreads();
        #pragma unroll
        for (int kk = 0; kk < 16; kk++) {
            float4 av0 = *(const float4*)&As[kk][ty * 8];
            float4 av1 = *(const float4*)&As[kk][ty * 8 + 4];
            ulonglong2 bv = *(const ulonglong2*)&Bs[kk][tx * 4];
            ull a;
            a = pack2(av0.x, av0.x); fma2(acc[0][0], a, bv.x); fma2(acc[0][1], a, bv.y);
            a = pack2(av0.y, av0.y); fma2(acc[1][0], a, bv.x); fma2(acc[1][1], a, bv.y);
            a = pack2(av0.z, av0.z); fma2(acc[2][0], a, bv.x); fma2(acc[2][1], a, bv.y);
            a = pack2(av0.w, av0.w); fma2(acc[3][0], a, bv.x); fma2(acc[3][1], a, bv.y);
            a = pack2(av1.x, av1.x); fma2(acc[4][0], a, bv.x); fma2(acc[4][1], a, bv.y);
            a = pack2(av1.y, av1.y); fma2(acc[5][0], a, bv.x); fma2(acc[5][1], a, bv.y);
            a = pack2(av1.z, av1.z); fma2(acc[6][0], a, bv.x); fma2(acc[6][1], a, bv.y);
            a = pack2(av1.w, av1.w); fma2(acc[7][0], a, bv.x); fma2(acc[7][1], a, bv.y);
        }
        __syncthreads();
    }
    const int m0 = bm * 128 + ty * 8, n0 = bn * 64 + tx * 4;
    #pragma unroll
    for (int i = 0; i < 8; i++) {
        #pragma unroll
        for (int p = 0; p < 2; p++) {
            float2 v = unpack2(acc[i][p]);
            int n = n0 + p * 2;
            v.x = thr(v.x + b2[n]);
            v.y = thr(v.y + b2[n + 1]);
            *(float2*)&g_emb[(size_t)(m0 + i) * EO + n] = v;
        }
    }
}

// ===========================================================================
// GEMM 2 (NT): xproj = emb @ W_ih^T + b_ih   M=4096 K=256 N=1536
//   Tile 128x128x16, 256 threads, 8x8 micro-tile (f32x2).
// ===========================================================================
__global__ __launch_bounds__(256) void gemm_xproj_kernel(
    const float* __restrict__ W_ih, const float* __restrict__ b_ih)
{
    __shared__ __align__(16) float As[16][132];
    __shared__ __align__(16) float Bs[16][132];

    const int bm = blockIdx.x, bn = blockIdx.y;
    const int t  = threadIdx.x;
    const int tx = t & 15, ty = t >> 4;
    const int row = t >> 2, seg = t & 3;

    ull acc[8][4] = {};

    for (int kt = 0; kt < EO; kt += 16) {
        #pragma unroll
        for (int i = 0; i < 2; i++) {
            int r = row + i * 64;
            float4 a4 = *(const float4*)(g_emb + (size_t)(bm * 128 + r) * EO + kt + seg * 4);
            As[seg * 4 + 0][r] = a4.x;
            As[seg * 4 + 1][r] = a4.y;
            As[seg * 4 + 2][r] = a4.z;
            As[seg * 4 + 3][r] = a4.w;
            float4 b4 = *(const float4*)(W_ih + (size_t)(bn * 128 + r) * EO + kt + seg * 4);
            Bs[seg * 4 + 0][r] = b4.x;
            Bs[seg * 4 + 1][r] = b4.y;
            Bs[seg * 4 + 2][r] = b4.z;
            Bs[seg * 4 + 3][r] = b4.w;
        }
        __syncthreads();
        #pragma unroll
        for (int kk = 0; kk < 16; kk++) {
            float4 av0 = *(const float4*)&As[kk][ty * 8];
            float4 av1 = *(const float4*)&As[kk][ty * 8 + 4];
            ulonglong2 b01 = *(const ulonglong2*)&Bs[kk][tx * 8];
            ulonglong2 b23 = *(const ulonglong2*)&Bs[kk][tx * 8 + 4];
            ull a;
            a = pack2(av0.x, av0.x); fma2(acc[0][0], a, b01.x); fma2(acc[0][1], a, b01.y); fma2(acc[0][2], a, b23.x); fma2(acc[0][3], a, b23.y);
            a = pack2(av0.y, av0.y); fma2(acc[1][0], a, b01.x); fma2(acc[1][1], a, b01.y); fma2(acc[1][2], a, b23.x); fma2(acc[1][3], a, b23.y);
            a = pack2(av0.z, av0.z); fma2(acc[2][0], a, b01.x); fma2(acc[2][1], a, b01.y); fma2(acc[2][2], a, b23.x); fma2(acc[2][3], a, b23.y);
            a = pack2(av0.w, av0.w); fma2(acc[3][0], a, b01.x); fma2(acc[3][1], a, b01.y); fma2(acc[3][2], a, b23.x); fma2(acc[3][3], a, b23.y);
            a = pack2(av1.x, av1.x); fma2(acc[4][0], a, b01.x); fma2(acc[4][1], a, b01.y); fma2(acc[4][2], a, b23.x); fma2(acc[4][3], a, b23.y);
            a = pack2(av1.y, av1.y); fma2(acc[5][0], a, b01.x); fma2(acc[5][1], a, b01.y); fma2(acc[5][2], a, b23.x); fma2(acc[5][3], a, b23.y);
            a = pack2(av1.z, av1.z); fma2(acc[6][0], a, b01.x); fma2(acc[6][1], a, b01.y); fma2(acc[6][2], a, b23.x); fma2(acc[6][3], a, b23.y);
            a = pack2(av1.w, av1.w); fma2(acc[7][0], a, b01.x); fma2(acc[7][1], a, b01.y); fma2(acc[7][2], a, b23.x); fma2(acc[7][3], a, b23.y);
        }
        __syncthreads();
    }
    const int m0 = bm * 128 + ty * 8, n0 = bn * 128 + tx * 8;
    #pragma unroll
    for (int i = 0; i < 8; i++) {
        #pragma unroll
        for (int p = 0; p < 4; p++) {
            float2 v = unpack2(acc[i][p]);
            int n = n0 + p * 2;
            v.x += b_ih[n];
            v.y += b_ih[n + 1];
            *(float2*)&g_xproj[(size_t)(m0 + i) * G3 + n] = v;
        }
    }
}

// ===========================================================================
// GRU recurrence: persistent kernel, 128 CTAs x 128 threads.
// CTA = (bg 0..3, jg 0..31): owns b in [bg*8,+8), j in [jg*16,+16).
// Thread = (jw 0..15, bh 0..1, ks 0..3): accumulates 4 batch rows (bh*4..+4)
// over interleaved k-slice kq === ks (mod 4). W columns XOR-swizzled by kq&3
// so ks lanes hit distinct bank groups. 2-round shfl reduce over ks.
// Per-bg grid barriers (groups of 32 CTAs), absolute flags + end reset.
// Head GEMM folded into the epilogue.
// ===========================================================================
#define GRU_NCTA   128
#define GRU_WS     (3 * 128 * 16 * 4)      // floats (96 KB)
#define GRU_HSTR   516
#define GRU_SMEMB  ((GRU_WS + 8 * GRU_HSTR) * 4)

__global__ __launch_bounds__(128, 1) void gru_kernel(
    const float* __restrict__ W_hh, const float* __restrict__ b_hh,
    const float* __restrict__ W3,   const float* __restrict__ b3,
    float* __restrict__ out)
{
    extern __shared__ __align__(16) float smem[];
    float* w_s = smem;                 // [gate][kq][col16][4], col swizzled
    float* h_s = smem + GRU_WS;        // [8][516]

    const int t   = threadIdx.x;
    const int bid = blockIdx.x;
    const int jg  = bid & 31;
    const int bg  = bid >> 5;

    // stage W_hh slice, columns swizzled by (kq & 3)
    for (int idx = t; idx < 3 * 16 * 128; idx += 128) {
        int kq = idx & 127;
        int jj = (idx >> 7) & 15;
        int g  = idx >> 11;
        float4 v = *(const float4*)(W_hh + ((size_t)(g * HID + jg * 16 + jj)) * HID + kq * 4);
        int c = (jj + (kq & 3)) & 15;
        *(float4*)(w_s + ((g * 128 + kq) * 16 + c) * 4) = v;
    }
    // zero-init our slice of h buffer 0
    g_h[0][(bg * 8 + (t >> 4)) * HID + jg * 16 + (t & 15)] = 0.0f;

    // ---- per-bg grid barrier: absolute index BI (1..SEQ+1) ----
    #define BG_BAR(BI) do {                                                    \
        __syncthreads();                                                       \
        if (jg == 0) {                                                         \
            if (t >= 1 && t < 32) {                                            \
                const unsigned* f = &g_bflags[(bg * 32 + t) * 32];             \
                while (ld_acq(f) < (unsigned)(BI)) { }                         \
            }                                                                  \
            __syncthreads();                                                   \
            if (t == 0) st_rel(&g_bgen[bg * 32], (unsigned)(BI));              \
        } else {                                                               \
            if (t == 0) {                                                      \
                st_rel(&g_bflags[bid * 32], (unsigned)(BI));                   \
                while (ld_acq(&g_bgen[bg * 32]) < (unsigned)(BI)) { }          \
            }                                                                  \
            __syncthreads();                                                   \
        }                                                                      \
    } while (0)

    BG_BAR(1);

    const int ks = t & 3;
    const int bh = (t >> 2) & 1;
    const int jw = t >> 3;                    // 0..15
    const int jglob = jg * 16 + jw;
    const int bfin  = bg * 8 + bh * 4 + ks;   // batch row this thread outputs

    const float bhr = b_hh[jglob];
    const float bhz = b_hh[HID + jglob];
    const float bhn = b_hh[2 * HID + jglob];

    const float* wcol = w_s + ((jw + ks) & 15) * 4;  // swizzled column base
    const float* hbase = h_s + bh * 4 * GRU_HSTR;

    for (int step = 0; step < SEQ; step++) {
        const float* cur = g_h[step & 1];
        float* nxt = g_h[(step & 1) ^ 1];

        // prefetch this step's xproj early (hide latency behind restage+MMA)
        size_t xb = ((size_t)(step * BAT + bfin)) * G3 + jglob;
        float xr = __ldcg(g_xproj + xb);
        float xz = __ldcg(g_xproj + xb + HID);
        float xn = __ldcg(g_xproj + xb + 2 * HID);

        // restage h slice (written by other SMs -> bypass L1)
        for (int r = t; r < 8 * 128; r += 128) {
            int rb = r >> 7, rk = r & 127;
            float4 v = __ldcg((const float4*)(cur + (size_t)(bg * 8 + rb) * HID + rk * 4));
            *(float4*)(h_s + rb * GRU_HSTR + rk * 4) = v;
        }
        __syncthreads();

        ull acc[4][3];
        #pragma unroll
        for (int m = 0; m < 4; m++) { acc[m][0] = 0; acc[m][1] = 0; acc[m][2] = 0; }

        #pragma unroll 2
        for (int i = 0; i < 32; i++) {
            const int kq = i * 4 + ks;
            const float* wp = wcol + kq * 64;
            ulonglong2 wr = *(const ulonglong2*)(wp);
            ulonglong2 wz = *(const ulonglong2*)(wp + 128 * 64);
            ulonglong2 wn = *(const ulonglong2*)(wp + 2 * 128 * 64);
            const float* hp = hbase + kq * 4;
            #pragma unroll
            for (int m = 0; m < 4; m++) {
                ulonglong2 hv = *(const ulonglong2*)(hp + m * GRU_HSTR);
                fma2(acc[m][0], hv.x, wr.x); fma2(acc[m][0], hv.y, wr.y);
                fma2(acc[m][1], hv.x, wz.x); fma2(acc[m][1], hv.y, wz.y);
                fma2(acc[m][2], hv.x, wn.x); fma2(acc[m][2], hv.y, wn.y);
            }
        }

        // collapse f32x2 halves, reduce over the 4 ks lanes (xor 1,2)
        float s[4][3];
        #pragma unroll
        for (int m = 0; m < 4; m++)
            #pragma unroll
            for (int g = 0; g < 3; g++) {
                float2 v = unpack2(acc[m][g]);
                s[m][g] = v.x + v.y;
            }
        #pragma unroll
        for (int off = 1; off <= 2; off <<= 1)
            #pragma unroll
            for (int m = 0; m < 4; m++)
                #pragma unroll
                for (int g = 0; g < 3; g++)
                    s[m][g] += __shfl_xor_sync(0xffffffffu, s[m][g], off);

        // thread finalizes b-index m == ks (predicated select)
        float ghr = 0.f, ghz = 0.f, ghn = 0.f;
        #pragma unroll
        for (int m = 0; m < 4; m++)
            if (m == ks) { ghr = s[m][0]; ghz = s[m][1]; ghn = s[m][2]; }
        ghr += bhr; ghz += bhz; ghn += bhn;

        float r = 1.0f / (1.0f + expf(-(xr + ghr)));
        float z = 1.0f / (1.0f + expf(-(xz + ghz)));
        float n = tanhf(xn + r * ghn);
        float hprev = h_s[(bh * 4 + ks) * GRU_HSTR + jglob];
        float hnew  = (1.0f - z) * n + z * hprev;

        nxt[(size_t)bfin * HID + jglob] = hnew;
        BG_BAR(step + 2);
    }

    // ---- head epilogue: out[b][o] = h[b] . W3[:,o] + b3[o] ----
    // CTA covers b in [bg*8,+8), o in [jg*8,+8). SEQ even -> h in g_h[0].
    for (int r = t; r < 8 * 128; r += 128) {
        int rb = r >> 7, rk = r & 127;
        float4 v = __ldcg((const float4*)(g_h[0] + (size_t)(bg * 8 + rb) * HID + rk * 4));
        *(float4*)(h_s + rb * GRU_HSTR + rk * 4) = v;
    }
    __syncthreads();

    {
        const int o  = t & 7;        // 0..7
        const int kc = t >> 3;       // 0..15, k-chunk of 32
        float part[8];
        #pragma unroll
        for (int bb = 0; bb < 8; bb++) part[bb] = 0.f;
        for (int kk = kc * 32; kk < kc * 32 + 32; kk++) {
            float w = __ldg(W3 + (size_t)kk * OUTD + jg * 8 + o);
            #pragma unroll
            for (int bb = 0; bb < 8; bb++)
                part[bb] = fmaf(h_s[bb * GRU_HSTR + kk], w, part[bb]);
        }
        float* red = w_s;  // scratch [16][8][8] (W no longer needed)
        #pragma unroll
        for (int bb = 0; bb < 8; bb++) red[(kc * 8 + o) * 8 + bb] = part[bb];
        __syncthreads();
        if (t < 64) {
            int oo = t & 7, bb = t >> 3;
            float sum = b3[jg * 8 + oo];
            #pragma unroll
            for (int k2 = 0; k2 < 16; k2++) sum += red[(k2 * 8 + oo) * 8 + bb];
            out[(bg * 8 + bb) * OUTD + jg * 8 + oo] = sum;
        }
    }

    // ---- barrier-state reset handshake (so next graph replay sees zeros) ----
    __syncthreads();
    if (jg == 0) {
        if (t >= 1 && t < 32) {
            const unsigned* f = &g_bflags[(bg * 32 + t) * 32];
            while (ld_acq(f) < (unsigned)(SEQ + 2)) { }
        }
        __syncthreads();
        if (t < 32) *(volatile unsigned*)&g_bflags[(bg * 32 + t) * 32] = 0u;
        if (t == 0) *(volatile unsigned*)&g_bgen[bg * 32] = 0u;
    } else {
        if (t == 0) st_rel(&g_bflags[bid * 32], (unsigned)(SEQ + 2));
    }
}

// ===========================================================================
extern "C" void kernel_launch(void* const* d_in, const int* in_sizes, int n_in,
                              void* d_out, int out_size)
{
    const int*   input = (const int*)  d_in[0];
    const float* W1    = (const float*)d_in[1];
    const float* b1    = (const float*)d_in[2];
    const float* W2    = (const float*)d_in[3];
    const float* b2    = (const float*)d_in[4];
    const float* W_ih  = (const float*)d_in[5];
    const float* W_hh  = (const float*)d_in[6];
    const float* b_ih  = (const float*)d_in[7];
    const float* b_hh  = (const float*)d_in[8];
    const float* W3    = (const float*)d_in[9];
    const float* b3    = (const float*)d_in[10];
    float* out = (float*)d_out;

    static int configured = 0;
    if (!configured) {
        cudaFuncSetAttribute(gru_kernel,
            cudaFuncAttributeMaxDynamicSharedMemorySize, GRU_SMEMB);
        configured = 1;
    }

    dim3 g1(MROWS / 128, EO / 64);
    gemm_embed_kernel<<<g1, 256>>>(input, W1, b1, W2, b2);

    dim3 g2(MROWS / 128, G3 / 128);
    gemm_xproj_kernel<<<g2, 256>>>(W_ih, b_ih);

    gru_kernel<<<GRU_NCTA, 128, GRU_SMEMB>>>(W_hh, b_hh, W3, b3, out);
}